// round 12
// baseline (speedup 1.0000x reference)
#include <cuda_runtime.h>
#include <cuda_fp16.h>
#include <math.h>
#include <stdint.h>

// ---------------- problem constants ----------------
#define IMGS 8
#define CIN  1024
#define P    1024
#define KC   28
#define KTOT 1052
#define KPAD 1088          // 17 K-stages of 64
#define COUT 2048
#define NB   4

// stage: 384 rows x 128B (rows 0-255: A(256xM), rows 256-383: B(128xN)), K=64/stage
#define STGB  49152
#define SMEMB (3 * STGB)   // 3-stage ring, 144KB -> 1 CTA/SM

// ---------------- scratch ----------------
__device__ float  g_ctx [IMGS * KC * P];
__device__ __align__(16) __half g_Wh[COUT * KPAD];
__device__ __align__(16) __half g_Xh[IMGS * P * KPAD];
__device__ __align__(16) __half g_Sh[(size_t)IMGS * P * COUT];
__device__ float  g_ssum[IMGS * P];
__device__ float  g_corr[(size_t)NB * P * P];              // scaled corr, [b][t][s]
__device__ unsigned g_smaxu[NB * P], g_tmaxu[NB * P];      // monotonic float keys
__device__ float  g_isx[NB * P], g_itx[NB * P];

__device__ const int c_dy[28] = {-3,-2,-1,0,1,2,3, -3,-2,-1,0,1,2,3, -3,-2,-1,0,1,2,3, 0,0,0,0,0,0,0};
__device__ const int c_dx[28] = {-3,-2,-1,0,1,2,3,  0, 0, 0,0,0,0,0,  3, 2, 1,0,-1,-2,-3, -3,-2,-1,0,1,2,3};

__device__ __forceinline__ const float* img_ptr(const float* src, const float* tgt, int img) {
    return (img < 4) ? (src + (size_t)img * CIN * P) : (tgt + (size_t)(img - 4) * CIN * P);
}
__device__ __forceinline__ uint32_t smem_u32(const void* p) {
    uint32_t a;
    asm("{ .reg .u64 t; cvta.to.shared.u64 t, %1; cvt.u32.u64 %0, t; }" : "=r"(a) : "l"(p));
    return a;
}
__device__ __forceinline__ void cp16(uint32_t dst, const void* src) {
    asm volatile("cp.async.cg.shared.global [%0], [%1], 16;" :: "r"(dst), "l"(src) : "memory");
}
__device__ __forceinline__ void ldsm4(uint32_t r[4], uint32_t a) {
    asm volatile("ldmatrix.sync.aligned.m8n8.x4.shared.b16 {%0,%1,%2,%3}, [%4];"
        : "=r"(r[0]), "=r"(r[1]), "=r"(r[2]), "=r"(r[3]) : "r"(a));
}
__device__ __forceinline__ void mma16816(float c[4], const uint32_t a[4], const uint32_t b[2]) {
    asm volatile("mma.sync.aligned.m16n8k16.row.col.f32.f16.f16.f32 "
        "{%0,%1,%2,%3},{%4,%5,%6,%7},{%8,%9},{%0,%1,%2,%3};"
        : "+f"(c[0]), "+f"(c[1]), "+f"(c[2]), "+f"(c[3])
        : "r"(a[0]), "r"(a[1]), "r"(a[2]), "r"(a[3]), "r"(b[0]), "r"(b[1]));
}
__device__ __forceinline__ unsigned fkey(float v) {
    unsigned b = __float_as_uint(v);
    return (b & 0x80000000u) ? ~b : (b | 0x80000000u);
}
__device__ __forceinline__ float funkey(unsigned k) {
    unsigned b = (k & 0x80000000u) ? (k & 0x7FFFFFFFu) : ~k;
    return __uint_as_float(b);
}

// ---------------- one 256x128x64 stage: 64x64 warp tiles, 8 ldsm -> 32 MMA per kk ----------------
__device__ __forceinline__ void compute_stage(uint32_t bb, const uint32_t aoff[4],
                                              const uint32_t boff[4], float acc[4][8][4])
{
#pragma unroll
    for (int kk = 0; kk < 4; kk++) {
        uint32_t a_h[4][4];
#pragma unroll
        for (int i = 0; i < 4; i++)
            ldsm4(a_h[i], (bb + aoff[i]) ^ (kk << 5));
#pragma unroll
        for (int jj = 0; jj < 4; jj++) {
            uint32_t bh4[4];
            ldsm4(bh4, (bb + boff[jj]) ^ (kk << 5));
#pragma unroll
            for (int i = 0; i < 4; i++) {
                mma16816(acc[i][jj * 2],     a_h[i], bh4 + 0);
                mma16816(acc[i][jj * 2 + 1], a_h[i], bh4 + 2);
            }
        }
    }
}

// ---------------- GEMM mainloop: CTA 256x128, 3-stage cp.async ring ----------------
__device__ __forceinline__ void gemm_ml(uint32_t smb,
    const __half* Ah, const __half* Bh, int lda, int ldb, int K, float acc[4][8][4])
{
    int tid = threadIdx.x, lane = tid & 31, wid = tid >> 5;
    int wm = wid & 3, wn = wid >> 2;
    int rr = tid >> 2;             // 0..63
    int cq = (tid & 3) * 2;        // chunk 0,2,4,6
    uint32_t ro  = (uint32_t)rr * 128;
    uint32_t sw0 = (uint32_t)((cq ^ (rr & 7)) * 16);
    uint32_t sw1 = (uint32_t)(((cq + 1) ^ (rr & 7)) * 16);
    const __half* pA0 = Ah + (size_t)rr * lda + cq * 8;
    const __half* pA1 = pA0 + (size_t)64 * lda;
    const __half* pA2 = pA0 + (size_t)128 * lda;
    const __half* pA3 = pA0 + (size_t)192 * lda;
    const __half* pB0 = Bh + (size_t)rr * ldb + cq * 8;
    const __half* pB1 = pB0 + (size_t)64 * ldb;

    uint32_t aoff[4], boff[4];
#pragma unroll
    for (int i = 0; i < 4; i++) {
        int row = wm * 64 + i * 16 + (lane & 15);
        aoff[i] = (uint32_t)row * 128 + (uint32_t)((((lane >> 4) ^ (lane & 7)) & 7) * 16);
    }
#pragma unroll
    for (int jj = 0; jj < 4; jj++) {
        int row = 256 + wn * 64 + jj * 16 + (lane & 7) + ((lane >> 4) & 1) * 8;
        boff[jj] = (uint32_t)row * 128 + (uint32_t)(((((lane >> 3) & 1) ^ (lane & 7)) & 7) * 16);
    }

#define ISSUE(buf, k0) do { \
        uint32_t bb = smb + (uint32_t)(buf) * STGB; \
        cp16(bb + ro + sw0,          pA0 + (k0)); \
        cp16(bb + ro + sw1,          pA0 + (k0) + 8); \
        cp16(bb + ro + 8192 + sw0,   pA1 + (k0)); \
        cp16(bb + ro + 8192 + sw1,   pA1 + (k0) + 8); \
        cp16(bb + ro + 16384 + sw0,  pA2 + (k0)); \
        cp16(bb + ro + 16384 + sw1,  pA2 + (k0) + 8); \
        cp16(bb + ro + 24576 + sw0,  pA3 + (k0)); \
        cp16(bb + ro + 24576 + sw1,  pA3 + (k0) + 8); \
        cp16(bb + ro + 32768 + sw0,  pB0 + (k0)); \
        cp16(bb + ro + 32768 + sw1,  pB0 + (k0) + 8); \
        cp16(bb + ro + 40960 + sw0,  pB1 + (k0)); \
        cp16(bb + ro + 40960 + sw1,  pB1 + (k0) + 8); \
        asm volatile("cp.async.commit_group;" ::: "memory"); \
    } while (0)

    int nst = K / 64;
    ISSUE(0, 0);
    ISSUE(1, 64);
    int buf = 0;
    for (int s = 0; s < nst; s++) {
        if (s + 1 < nst) { asm volatile("cp.async.wait_group 1;" ::: "memory"); }
        else             { asm volatile("cp.async.wait_group 0;" ::: "memory"); }
        __syncthreads();
        int nx = s + 2;
        if (nx < nst) ISSUE(nx % 3, nx * 64);
        compute_stage(smb + (uint32_t)buf * STGB, aoff, boff, acc);
        buf = (buf + 1 == 3) ? 0 : buf + 1;
    }
#undef ISSUE
}

// ---------------- kernel 1: context channels with fused local norms ----------------
__global__ void k_ctx(const float* __restrict__ src, const float* __restrict__ tgt) {
    int img = blockIdx.x, y = blockIdx.y;
    const float* f = img_ptr(src, tgt, img);
    int lane = threadIdx.x & 31, w = threadIdx.x >> 5;
    __shared__ float tile[8][7][32];
    __shared__ float red[28][8][32];
    __shared__ float redn[7][8][32];
    __shared__ float invl[7][32];
    float acc[28];
    float accn[7];
#pragma unroll
    for (int k = 0; k < 28; k++) acc[k] = 0.f;
#pragma unroll
    for (int d = 0; d < 7; d++) accn[d] = 0.f;

    for (int c = w; c < CIN; c += 8) {
#pragma unroll
        for (int dy = 0; dy < 7; dy++) {
            int yy = y + dy - 3;
            float v = (yy >= 0 && yy < 32) ? f[c * P + yy * 32 + lane] : 0.f;
            tile[w][dy][lane] = v;
            accn[dy] = fmaf(v, v, accn[dy]);
        }
        __syncwarp();
        float v0 = tile[w][3][lane];
#pragma unroll
        for (int k = 0; k < 28; k++) {
            int xx = lane + c_dx[k];
            float v = (xx >= 0 && xx < 32) ? tile[w][c_dy[k] + 3][xx] : 0.f;
            acc[k] = fmaf(v0, v, acc[k]);
        }
        __syncwarp();
    }
#pragma unroll
    for (int k = 0; k < 28; k++) red[k][w][lane] = acc[k];
#pragma unroll
    for (int d = 0; d < 7; d++) redn[d][w][lane] = accn[d];
    __syncthreads();

    if (threadIdx.x < 7 * 32) {
        int d = threadIdx.x >> 5, x = threadIdx.x & 31;
        float s = 0.f;
#pragma unroll
        for (int i = 0; i < 8; i++) s += redn[d][i][x];
        invl[d][x] = 1.f / fmaxf(sqrtf(s), 1e-12f);
    }
    __syncthreads();

    for (int idx = threadIdx.x; idx < 28 * 32; idx += 256) {
        int k = idx >> 5, x = idx & 31;
        float s = 0.f;
#pragma unroll
        for (int i = 0; i < 8; i++) s += red[k][i][x];
        int yy = y + c_dy[k], xx = x + c_dx[k];
        float o = 0.f;
        if (yy >= 0 && yy < 32 && xx >= 0 && xx < 32)
            o = s * invl[3][x] * invl[c_dy[k] + 3][xx];
        g_ctx[((size_t)img * KC + k) * P + y * 32 + x] = o;
    }
}

// ---------------- kernel 2: transpose inputs (z<8) / pad W + zero scratch (z==8) ----------------
__global__ void k_xtw(const float* __restrict__ src, const float* __restrict__ tgt,
                      const float* __restrict__ W) {
    int img = blockIdx.z;
    int tid = threadIdx.y * 32 + threadIdx.x;
    if (img == 8) {
        int gid = (blockIdx.y * 34 + blockIdx.x) * 256 + tid;
        if (gid < IMGS * P) g_ssum[gid] = 0.f;
        if (gid < NB * P) { g_smaxu[gid] = 0u; g_tmaxu[gid] = 0u; }
        size_t base = ((size_t)gid) * 8;
        if (base < (size_t)COUT * KPAD) {
#pragma unroll
            for (int u = 0; u < 8; u++) {
                size_t idx = base + u;
                int o = (int)(idx / KPAD);
                int k = (int)(idx - (size_t)o * KPAD);
                float v = (k < KTOT) ? W[(size_t)o * KTOT + k] : 0.f;
                g_Wh[idx] = __float2half_rn(v);
            }
        }
        return;
    }
    int cblk = blockIdx.x, pblk = blockIdx.y;
    const float* f = img_ptr(src, tgt, img);
    __shared__ float tile[32][33];
    int tx = threadIdx.x;
    for (int r = threadIdx.y; r < 32; r += 8) {
        int c = cblk * 32 + r, p = pblk * 32 + tx;
        float v = 0.f;
        if (c < CIN) v = f[(size_t)c * P + p];
        else if (c < KTOT) v = g_ctx[((size_t)img * KC + (c - CIN)) * P + p];
        tile[r][tx] = v;
    }
    __syncthreads();
    for (int r = threadIdx.y; r < 32; r += 8) {
        int p = pblk * 32 + r, c = cblk * 32 + tx;
        g_Xh[((size_t)img * P + p) * KPAD + c] = __float2half_rn(tile[tx][r]);
    }
}

// ---------------- conv GEMM (CTA 256x128, plain fp16) ----------------
__global__ void __launch_bounds__(256, 1) k_conv(const float* __restrict__ bias) {
    extern __shared__ char smc[];
    __shared__ float sss[256];
    uint32_t smb = (smem_u32(smc) + 127u) & ~127u;
    int img = blockIdx.z, bm = blockIdx.y * 256, bn = blockIdx.x * 128;  // bm: p, bn: o
    const __half* Ah = g_Xh + ((size_t)img * P + bm) * KPAD;
    const __half* Bh = g_Wh + (size_t)bn * KPAD;
    float acc[4][8][4] = {};
    gemm_ml(smb, Ah, Bh, KPAD, KPAD, KPAD, acc);

    if (threadIdx.x < 256) sss[threadIdx.x] = 0.f;
    __syncthreads();

    int lane = threadIdx.x & 31, wid = threadIdx.x >> 5, wm = wid & 3, wn = wid >> 2;
    __half* Shp = g_Sh + (size_t)img * P * COUT;
#pragma unroll
    for (int i = 0; i < 4; i++) {
        int pl0 = wm * 64 + i * 16 + (lane >> 2);
        int p0 = bm + pl0;
        float q0 = 0.f, q1 = 0.f;
#pragma unroll
        for (int j = 0; j < 8; j++) {
            int o = bn + wn * 64 + j * 8 + 2 * (lane & 3);
            float2 bb = *(const float2*)(bias + o);
            float a0 = fmaxf(acc[i][j][0] + bb.x, 0.f);
            float a1 = fmaxf(acc[i][j][1] + bb.y, 0.f);
            float a2 = fmaxf(acc[i][j][2] + bb.x, 0.f);
            float a3 = fmaxf(acc[i][j][3] + bb.y, 0.f);
            q0 = fmaf(a0, a0, fmaf(a1, a1, q0));
            q1 = fmaf(a2, a2, fmaf(a3, a3, q1));
            *(__half2*)(Shp + (size_t)p0 * COUT + o)       = __halves2half2(__float2half_rn(a0), __float2half_rn(a1));
            *(__half2*)(Shp + (size_t)(p0 + 8) * COUT + o) = __halves2half2(__float2half_rn(a2), __float2half_rn(a3));
        }
        atomicAdd(&sss[pl0], q0);
        atomicAdd(&sss[pl0 + 8], q1);
    }
    __syncthreads();
    atomicAdd(&g_ssum[img * P + bm + threadIdx.x], sss[threadIdx.x]);
}

// ---------------- corr GEMM (CTA 256x128): scaled corr [b][t][s] + fused tile maxes ----------------
__global__ void __launch_bounds__(256, 1) k_corr() {
    extern __shared__ char smc[];
    __shared__ unsigned su[256], tu[128];
    uint32_t smb = (smem_u32(smc) + 127u) & ~127u;
    int b = blockIdx.z, bm = blockIdx.y * 256, bn = blockIdx.x * 128;  // bm: s, bn: t
    const __half* Ah = g_Sh + ((size_t)b * P + bm) * COUT;
    const __half* Bh = g_Sh + ((size_t)(4 + b) * P + bn) * COUT;
    float acc[4][8][4] = {};
    gemm_ml(smb, Ah, Bh, COUT, COUT, COUT, acc);

    su[threadIdx.x] = 0u;
    if (threadIdx.x < 128) tu[threadIdx.x] = 0u;
    __syncthreads();

    int lane = threadIdx.x & 31, wid = threadIdx.x >> 5, wm = wid & 3, wn = wid >> 2;
    const float* ssums = g_ssum + b * P;
    const float* ssumt = g_ssum + (4 + b) * P;
    float* C = g_corr + (size_t)b * P * P;
#pragma unroll
    for (int i = 0; i < 4; i++) {
        int sl0 = wm * 64 + i * 16 + (lane >> 2);
        int s0 = bm + sl0;
        float is0 = rsqrtf(ssums[s0] + 1e-6f), is1 = rsqrtf(ssums[s0 + 8] + 1e-6f);
        unsigned ks0 = 0u, ks1 = 0u;
#pragma unroll
        for (int j = 0; j < 8; j++) {
            int tl0 = wn * 64 + j * 8 + 2 * (lane & 3);
            int t0 = bn + tl0;
            float it0 = rsqrtf(ssumt[t0] + 1e-6f), it1 = rsqrtf(ssumt[t0 + 1] + 1e-6f);
            float c00 = acc[i][j][0] * is0 * it0;
            float c01 = acc[i][j][1] * is0 * it1;
            float c10 = acc[i][j][2] * is1 * it0;
            float c11 = acc[i][j][3] * is1 * it1;
            C[(size_t)t0 * P + s0]           = c00;
            C[(size_t)(t0 + 1) * P + s0]     = c01;
            C[(size_t)t0 * P + s0 + 8]       = c10;
            C[(size_t)(t0 + 1) * P + s0 + 8] = c11;
            unsigned k00 = fkey(c00), k01 = fkey(c01), k10 = fkey(c10), k11 = fkey(c11);
            ks0 = max(ks0, max(k00, k01));
            ks1 = max(ks1, max(k10, k11));
            atomicMax(&tu[tl0],     max(k00, k10));
            atomicMax(&tu[tl0 + 1], max(k01, k11));
        }
        atomicMax(&su[sl0], ks0);
        atomicMax(&su[sl0 + 8], ks1);
    }
    __syncthreads();
    atomicMax(&g_smaxu[b * P + bm + threadIdx.x], su[threadIdx.x]);
    if (threadIdx.x < 128)
        atomicMax(&g_tmaxu[b * P + bn + threadIdx.x], tu[threadIdx.x]);
}

// ---------------- keys -> guarded reciprocals ----------------
__global__ void k_recip() {
    int i = blockIdx.x * 256 + threadIdx.x;
    if (i < NB * P) {
        float v = funkey(g_smaxu[i]); if (v == 0.f) v = 1e-30f;
        g_isx[i] = 1.f / v;
        float w = funkey(g_tmaxu[i]); if (w == 0.f) w = 1e-30f;
        g_itx[i] = 1.f / w;
    }
}

// ---------------- fused filter + resize + softmax + soft-argmax + flow ----------------
__global__ void __launch_bounds__(256) k_flow(float* __restrict__ out) {
    int tx = blockIdx.x, ty = blockIdx.y, b = blockIdx.z;
    int tid = threadIdx.x;
    const float sc = 31.f / 63.f;
    float fy = ty * sc; int y0 = (int)fy; int y1 = min(y0 + 1, 31); float wy = fy - (float)y0;
    float fx = tx * sc; int x0 = (int)fx; int x1 = min(x0 + 1, 31); float wx = fx - (float)x0;
    int t00 = y0 * 32 + x0, t01 = y0 * 32 + x1, t10 = y1 * 32 + x0, t11 = y1 * 32 + x1;
    const float* C = g_corr + (size_t)b * P * P;
    const float* r00 = C + (size_t)t00 * P;
    const float* r01 = C + (size_t)t01 * P;
    const float* r10 = C + (size_t)t10 * P;
    const float* r11 = C + (size_t)t11 * P;
    float ww00 = (1.f - wy) * (1.f - wx) * g_itx[b * P + t00];
    float ww01 = (1.f - wy) * wx         * g_itx[b * P + t01];
    float ww10 = wy * (1.f - wx)         * g_itx[b * P + t10];
    float ww11 = wy * wx                 * g_itx[b * P + t11];
    const float* isx = g_isx + b * P;
    __shared__ float m[P];
    for (int s = tid; s < P; s += 256) {
        float v00 = r00[s], v01 = r01[s], v10 = r10[s], v11 = r11[s];
        float a = ww00 * v00 * v00 * v00 + ww01 * v01 * v01 * v01
                + ww10 * v10 * v10 * v10 + ww11 * v11 * v11 * v11;
        m[s] = a * isx[s];
    }
    __syncthreads();
    float mx = -INFINITY;
    for (int s = tid; s < P; s += 256) mx = fmaxf(mx, m[s]);
    __shared__ float rd[8];
#pragma unroll
    for (int o = 16; o > 0; o >>= 1) mx = fmaxf(mx, __shfl_xor_sync(0xffffffffu, mx, o));
    if ((tid & 31) == 0) rd[tid >> 5] = mx;
    __syncthreads();
    float M = -INFINITY;
#pragma unroll
    for (int i = 0; i < 8; i++) M = fmaxf(M, rd[i]);
    float sum = 0.f, sx = 0.f, sy = 0.f;
    for (int s = tid; s < 4096; s += 256) {
        int i = s >> 6, j = s & 63;
        float gy = i * sc; int yy0 = (int)gy; int yy1 = min(yy0 + 1, 31); float a = gy - (float)yy0;
        float gx = j * sc; int xx0 = (int)gx; int xx1 = min(xx0 + 1, 31); float bq = gx - (float)xx0;
        float v = (1.f - a) * ((1.f - bq) * m[yy0 * 32 + xx0] + bq * m[yy0 * 32 + xx1])
                +        a  * ((1.f - bq) * m[yy1 * 32 + xx0] + bq * m[yy1 * 32 + xx1]);
        float e = __expf((v - M) * 50.f);
        sum += e;
        sx = fmaf(e, -1.f + j * (2.f / 63.f), sx);
        sy = fmaf(e, -1.f + i * (2.f / 63.f), sy);
    }
    __shared__ float rs[8], rx[8], ry[8];
#pragma unroll
    for (int o = 16; o > 0; o >>= 1) {
        sum += __shfl_xor_sync(0xffffffffu, sum, o);
        sx  += __shfl_xor_sync(0xffffffffu, sx,  o);
        sy  += __shfl_xor_sync(0xffffffffu, sy,  o);
    }
    if ((tid & 31) == 0) { rs[tid >> 5] = sum; rx[tid >> 5] = sx; ry[tid >> 5] = sy; }
    __syncthreads();
    if (tid == 0) {
        float S = 0.f, X = 0.f, Y = 0.f;
#pragma unroll
        for (int i = 0; i < 8; i++) { S += rs[i]; X += rx[i]; Y += ry[i]; }
        float gx_ = X / S, gy_ = Y / S;
        out[(size_t)b * 8192 + (size_t)ty * 64 + tx]        = (gx_ + 1.f) * 31.5f - (float)tx;
        out[(size_t)b * 8192 + 4096 + (size_t)ty * 64 + tx] = (gy_ + 1.f) * 31.5f - (float)ty;
    }
}

// ---------------- launch ----------------
extern "C" void kernel_launch(void* const* d_in, const int* in_sizes, int n_in,
                              void* d_out, int out_size) {
    const float* src  = (const float*)d_in[0];
    const float* tgt  = (const float*)d_in[1];
    const float* W    = (const float*)d_in[2];
    const float* bias = (const float*)d_in[3];
    float* out = (float*)d_out;

    cudaFuncSetAttribute(k_conv, cudaFuncAttributeMaxDynamicSharedMemorySize, SMEMB);
    cudaFuncSetAttribute(k_corr, cudaFuncAttributeMaxDynamicSharedMemorySize, SMEMB);

    k_ctx  <<<dim3(8, 32), 256>>>(src, tgt);
    k_xtw  <<<dim3(34, 32, 9), dim3(32, 8)>>>(src, tgt, W);
    k_conv <<<dim3(16, 4, 8), 256, SMEMB>>>(bias);
    k_corr <<<dim3(8, 4, 4), 256, SMEMB>>>();
    k_recip<<<16, 256>>>();
    k_flow <<<dim3(64, 64, 4), 256>>>(out);
}

// round 13
// speedup vs baseline: 1.0393x; 1.0393x over previous
#include <cuda_runtime.h>
#include <cuda_fp16.h>
#include <math.h>
#include <stdint.h>

// ---------------- problem constants ----------------
#define IMGS 8
#define CIN  1024
#define P    1024
#define KC   28
#define KTOT 1052
#define KPAD 1088          // 17 K-stages of 64
#define COUT 2048
#define NB   4

// stage: 256 rows x 128B (rows 0-127: A, rows 128-255: B), K=64 per stage
#define STGB  32768
#define SMEMB (3 * STGB)   // 3-stage ring, 96KB -> 2 CTAs/SM

// ---------------- scratch ----------------
__device__ float  g_ctx [IMGS * KC * P];
__device__ __align__(16) __half g_Wh[COUT * KPAD];
__device__ __align__(16) __half g_Xh[IMGS * P * KPAD];
__device__ __align__(16) __half g_Sh[(size_t)IMGS * P * COUT];
__device__ float  g_ssum[IMGS * P];
__device__ float  g_corr[(size_t)NB * P * P];              // scaled corr, [b][t][s]
__device__ unsigned g_smaxu[NB * P], g_tmaxu[NB * P];      // monotonic float keys
__device__ float  g_isx[NB * P], g_itx[NB * P];

__device__ const int c_dy[28] = {-3,-2,-1,0,1,2,3, -3,-2,-1,0,1,2,3, -3,-2,-1,0,1,2,3, 0,0,0,0,0,0,0};
__device__ const int c_dx[28] = {-3,-2,-1,0,1,2,3,  0, 0, 0,0,0,0,0,  3, 2, 1,0,-1,-2,-3, -3,-2,-1,0,1,2,3};

__device__ __forceinline__ const float* img_ptr(const float* src, const float* tgt, int img) {
    return (img < 4) ? (src + (size_t)img * CIN * P) : (tgt + (size_t)(img - 4) * CIN * P);
}
__device__ __forceinline__ uint32_t smem_u32(const void* p) {
    uint32_t a;
    asm("{ .reg .u64 t; cvta.to.shared.u64 t, %1; cvt.u32.u64 %0, t; }" : "=r"(a) : "l"(p));
    return a;
}
__device__ __forceinline__ void cp16(uint32_t dst, const void* src) {
    asm volatile("cp.async.cg.shared.global [%0], [%1], 16;" :: "r"(dst), "l"(src) : "memory");
}
__device__ __forceinline__ void ldsm4(uint32_t r[4], uint32_t a) {
    asm volatile("ldmatrix.sync.aligned.m8n8.x4.shared.b16 {%0,%1,%2,%3}, [%4];"
        : "=r"(r[0]), "=r"(r[1]), "=r"(r[2]), "=r"(r[3]) : "r"(a));
}
__device__ __forceinline__ void mma16816(float c[4], const uint32_t a[4], const uint32_t b[2]) {
    asm volatile("mma.sync.aligned.m16n8k16.row.col.f32.f16.f16.f32 "
        "{%0,%1,%2,%3},{%4,%5,%6,%7},{%8,%9},{%0,%1,%2,%3};"
        : "+f"(c[0]), "+f"(c[1]), "+f"(c[2]), "+f"(c[3])
        : "r"(a[0]), "r"(a[1]), "r"(a[2]), "r"(a[3]), "r"(b[0]), "r"(b[1]));
}
__device__ __forceinline__ unsigned fkey(float v) {
    unsigned b = __float_as_uint(v);
    return (b & 0x80000000u) ? ~b : (b | 0x80000000u);
}
__device__ __forceinline__ float funkey(unsigned k) {
    unsigned b = (k & 0x80000000u) ? (k & 0x7FFFFFFFu) : ~k;
    return __uint_as_float(b);
}

// ---------------- one 128x128x64 stage of MMA from swizzled smem ----------------
__device__ __forceinline__ void compute_stage(uint32_t bb, const uint32_t aoff[2],
                                              const uint32_t boff[4], float acc[2][8][4])
{
#pragma unroll
    for (int kk = 0; kk < 4; kk++) {
        uint32_t a_h[2][4];
#pragma unroll
        for (int i = 0; i < 2; i++)
            ldsm4(a_h[i], (bb + aoff[i]) ^ (kk << 5));
#pragma unroll
        for (int jj = 0; jj < 4; jj++) {
            uint32_t bh4[4];
            ldsm4(bh4, (bb + boff[jj]) ^ (kk << 5));
#pragma unroll
            for (int i = 0; i < 2; i++) {
                mma16816(acc[i][jj * 2],     a_h[i], bh4 + 0);
                mma16816(acc[i][jj * 2 + 1], a_h[i], bh4 + 2);
            }
        }
    }
}

// ---------------- GEMM mainloop: 3-stage cp.async ring, K=64/stage, swizzled smem ----------------
__device__ __forceinline__ void gemm_ml(uint32_t smb,
    const __half* Ah, const __half* Bh, int lda, int ldb, int K, float acc[2][8][4])
{
    int tid = threadIdx.x, lane = tid & 31, wid = tid >> 5;
    int wm = wid & 3, wn = wid >> 2;
    int rr = tid >> 2;             // 0..63
    int cq = (tid & 3) * 2;        // chunk 0,2,4,6
    uint32_t ro  = (uint32_t)rr * 128;
    uint32_t sw0 = (uint32_t)((cq ^ (rr & 7)) * 16);
    uint32_t sw1 = (uint32_t)(((cq + 1) ^ (rr & 7)) * 16);
    const __half* pA0 = Ah + (size_t)rr * lda + cq * 8;
    const __half* pA1 = Ah + (size_t)(rr + 64) * lda + cq * 8;
    const __half* pB0 = Bh + (size_t)rr * ldb + cq * 8;
    const __half* pB1 = Bh + (size_t)(rr + 64) * ldb + cq * 8;

    uint32_t aoff[2], boff[4];
#pragma unroll
    for (int i = 0; i < 2; i++) {
        int row = wm * 32 + i * 16 + (lane & 15);
        aoff[i] = (uint32_t)row * 128 + (uint32_t)((((lane >> 4) ^ (lane & 7)) & 7) * 16);
    }
#pragma unroll
    for (int jj = 0; jj < 4; jj++) {
        int row = 128 + wn * 64 + jj * 16 + (lane & 7) + ((lane >> 4) & 1) * 8;
        boff[jj] = (uint32_t)row * 128 + (uint32_t)(((((lane >> 3) & 1) ^ (lane & 7)) & 7) * 16);
    }

#define ISSUE(buf, k0) do { \
        uint32_t bb = smb + (uint32_t)(buf) * STGB; \
        cp16(bb + ro + sw0,          pA0 + (k0)); \
        cp16(bb + ro + sw1,          pA0 + (k0) + 8); \
        cp16(bb + ro + 8192 + sw0,   pA1 + (k0)); \
        cp16(bb + ro + 8192 + sw1,   pA1 + (k0) + 8); \
        cp16(bb + ro + 16384 + sw0,  pB0 + (k0)); \
        cp16(bb + ro + 16384 + sw1,  pB0 + (k0) + 8); \
        cp16(bb + ro + 24576 + sw0,  pB1 + (k0)); \
        cp16(bb + ro + 24576 + sw1,  pB1 + (k0) + 8); \
        asm volatile("cp.async.commit_group;" ::: "memory"); \
    } while (0)

    int nst = K / 64;
    ISSUE(0, 0);
    ISSUE(1, 64);
    int buf = 0;
    for (int s = 0; s < nst; s++) {
        if (s + 1 < nst) { asm volatile("cp.async.wait_group 1;" ::: "memory"); }
        else             { asm volatile("cp.async.wait_group 0;" ::: "memory"); }
        __syncthreads();
        int nx = s + 2;
        if (nx < nst) ISSUE(nx % 3, nx * 64);
        compute_stage(smb + (uint32_t)buf * STGB, aoff, boff, acc);
        buf = (buf + 1 == 3) ? 0 : buf + 1;
    }
#undef ISSUE
}

// ---------------- kernel 1: context channels with fused local norms ----------------
__global__ void k_ctx(const float* __restrict__ src, const float* __restrict__ tgt) {
    int img = blockIdx.x, y = blockIdx.y;
    const float* f = img_ptr(src, tgt, img);
    int lane = threadIdx.x & 31, w = threadIdx.x >> 5;
    __shared__ float tile[8][7][32];
    __shared__ float red[28][8][32];
    __shared__ float redn[7][8][32];
    __shared__ float invl[7][32];
    float acc[28];
    float accn[7];
#pragma unroll
    for (int k = 0; k < 28; k++) acc[k] = 0.f;
#pragma unroll
    for (int d = 0; d < 7; d++) accn[d] = 0.f;

    for (int c = w; c < CIN; c += 8) {
#pragma unroll
        for (int dy = 0; dy < 7; dy++) {
            int yy = y + dy - 3;
            float v = (yy >= 0 && yy < 32) ? f[c * P + yy * 32 + lane] : 0.f;
            tile[w][dy][lane] = v;
            accn[dy] = fmaf(v, v, accn[dy]);
        }
        __syncwarp();
        float v0 = tile[w][3][lane];
#pragma unroll
        for (int k = 0; k < 28; k++) {
            int xx = lane + c_dx[k];
            float v = (xx >= 0 && xx < 32) ? tile[w][c_dy[k] + 3][xx] : 0.f;
            acc[k] = fmaf(v0, v, acc[k]);
        }
        __syncwarp();
    }
#pragma unroll
    for (int k = 0; k < 28; k++) red[k][w][lane] = acc[k];
#pragma unroll
    for (int d = 0; d < 7; d++) redn[d][w][lane] = accn[d];
    __syncthreads();

    if (threadIdx.x < 7 * 32) {
        int d = threadIdx.x >> 5, x = threadIdx.x & 31;
        float s = 0.f;
#pragma unroll
        for (int i = 0; i < 8; i++) s += redn[d][i][x];
        invl[d][x] = 1.f / fmaxf(sqrtf(s), 1e-12f);
    }
    __syncthreads();

    for (int idx = threadIdx.x; idx < 28 * 32; idx += 256) {
        int k = idx >> 5, x = idx & 31;
        float s = 0.f;
#pragma unroll
        for (int i = 0; i < 8; i++) s += red[k][i][x];
        int yy = y + c_dy[k], xx = x + c_dx[k];
        float o = 0.f;
        if (yy >= 0 && yy < 32 && xx >= 0 && xx < 32)
            o = s * invl[3][x] * invl[c_dy[k] + 3][xx];
        g_ctx[((size_t)img * KC + k) * P + y * 32 + x] = o;
    }
}

// ---------------- kernel 2: transpose inputs (z<8) / pad W + zero scratch (z==8) ----------------
__global__ void k_xtw(const float* __restrict__ src, const float* __restrict__ tgt,
                      const float* __restrict__ W) {
    int img = blockIdx.z;
    int tid = threadIdx.y * 32 + threadIdx.x;
    if (img == 8) {
        int gid = (blockIdx.y * 34 + blockIdx.x) * 256 + tid;
        if (gid < IMGS * P) g_ssum[gid] = 0.f;
        if (gid < NB * P) { g_smaxu[gid] = 0u; g_tmaxu[gid] = 0u; }
        size_t base = ((size_t)gid) * 8;
        if (base < (size_t)COUT * KPAD) {
#pragma unroll
            for (int u = 0; u < 8; u++) {
                size_t idx = base + u;
                int o = (int)(idx / KPAD);
                int k = (int)(idx - (size_t)o * KPAD);
                float v = (k < KTOT) ? W[(size_t)o * KTOT + k] : 0.f;
                g_Wh[idx] = __float2half_rn(v);
            }
        }
        return;
    }
    int cblk = blockIdx.x, pblk = blockIdx.y;
    const float* f = img_ptr(src, tgt, img);
    __shared__ float tile[32][33];
    int tx = threadIdx.x;
    for (int r = threadIdx.y; r < 32; r += 8) {
        int c = cblk * 32 + r, p = pblk * 32 + tx;
        float v = 0.f;
        if (c < CIN) v = f[(size_t)c * P + p];
        else if (c < KTOT) v = g_ctx[((size_t)img * KC + (c - CIN)) * P + p];
        tile[r][tx] = v;
    }
    __syncthreads();
    for (int r = threadIdx.y; r < 32; r += 8) {
        int p = pblk * 32 + r, c = cblk * 32 + tx;
        g_Xh[((size_t)img * P + p) * KPAD + c] = __float2half_rn(tile[tx][r]);
    }
}

// ---------------- conv GEMM (plain fp16: Xh * Wh) ----------------
__global__ void __launch_bounds__(256, 2) k_conv(const float* __restrict__ bias) {
    extern __shared__ char smc[];
    __shared__ float sss[128];
    uint32_t smb = (smem_u32(smc) + 127u) & ~127u;
    int img = blockIdx.z, bm = blockIdx.y * 128, bn = blockIdx.x * 128;  // bm: p, bn: o
    const __half* Ah = g_Xh + ((size_t)img * P + bm) * KPAD;
    const __half* Bh = g_Wh + (size_t)bn * KPAD;
    float acc[2][8][4] = {};
    gemm_ml(smb, Ah, Bh, KPAD, KPAD, KPAD, acc);

    if (threadIdx.x < 128) sss[threadIdx.x] = 0.f;
    __syncthreads();

    int lane = threadIdx.x & 31, wid = threadIdx.x >> 5, wm = wid & 3, wn = wid >> 2;
    __half* Shp = g_Sh + (size_t)img * P * COUT;
#pragma unroll
    for (int i = 0; i < 2; i++) {
        int pl0 = wm * 32 + i * 16 + (lane >> 2);
        int p0 = bm + pl0;
        float q0 = 0.f, q1 = 0.f;
#pragma unroll
        for (int j = 0; j < 8; j++) {
            int o = bn + wn * 64 + j * 8 + 2 * (lane & 3);
            float2 bb = *(const float2*)(bias + o);
            float a0 = fmaxf(acc[i][j][0] + bb.x, 0.f);
            float a1 = fmaxf(acc[i][j][1] + bb.y, 0.f);
            float a2 = fmaxf(acc[i][j][2] + bb.x, 0.f);
            float a3 = fmaxf(acc[i][j][3] + bb.y, 0.f);
            q0 = fmaf(a0, a0, fmaf(a1, a1, q0));
            q1 = fmaf(a2, a2, fmaf(a3, a3, q1));
            *(__half2*)(Shp + (size_t)p0 * COUT + o)       = __halves2half2(__float2half_rn(a0), __float2half_rn(a1));
            *(__half2*)(Shp + (size_t)(p0 + 8) * COUT + o) = __halves2half2(__float2half_rn(a2), __float2half_rn(a3));
        }
        atomicAdd(&sss[pl0], q0);
        atomicAdd(&sss[pl0 + 8], q1);
    }
    __syncthreads();
    if (threadIdx.x < 128) atomicAdd(&g_ssum[img * P + bm + threadIdx.x], sss[threadIdx.x]);
}

// ---------------- corr GEMM (plain fp16): scaled corr [b][t][s] + fused tile maxes ----------------
__global__ void __launch_bounds__(256, 2) k_corr() {
    extern __shared__ char smc[];
    __shared__ unsigned su[128], tu[128];
    uint32_t smb = (smem_u32(smc) + 127u) & ~127u;
    int b = blockIdx.z, bm = blockIdx.y * 128, bn = blockIdx.x * 128;  // bm: s, bn: t
    const __half* Ah = g_Sh + ((size_t)b * P + bm) * COUT;
    const __half* Bh = g_Sh + ((size_t)(4 + b) * P + bn) * COUT;
    float acc[2][8][4] = {};
    gemm_ml(smb, Ah, Bh, COUT, COUT, COUT, acc);

    if (threadIdx.x < 128) { su[threadIdx.x] = 0u; tu[threadIdx.x] = 0u; }
    __syncthreads();

    int lane = threadIdx.x & 31, wid = threadIdx.x >> 5, wm = wid & 3, wn = wid >> 2;
    const float* ssums = g_ssum + b * P;
    const float* ssumt = g_ssum + (4 + b) * P;
    float* C = g_corr + (size_t)b * P * P;
#pragma unroll
    for (int i = 0; i < 2; i++) {
        int sl0 = wm * 32 + i * 16 + (lane >> 2);
        int s0 = bm + sl0;
        float is0 = rsqrtf(ssums[s0] + 1e-6f), is1 = rsqrtf(ssums[s0 + 8] + 1e-6f);
        unsigned ks0 = 0u, ks1 = 0u;
#pragma unroll
        for (int j = 0; j < 8; j++) {
            int tl0 = wn * 64 + j * 8 + 2 * (lane & 3);
            int t0 = bn + tl0;
            float it0 = rsqrtf(ssumt[t0] + 1e-6f), it1 = rsqrtf(ssumt[t0 + 1] + 1e-6f);
            float c00 = acc[i][j][0] * is0 * it0;
            float c01 = acc[i][j][1] * is0 * it1;
            float c10 = acc[i][j][2] * is1 * it0;
            float c11 = acc[i][j][3] * is1 * it1;
            C[(size_t)t0 * P + s0]           = c00;
            C[(size_t)(t0 + 1) * P + s0]     = c01;
            C[(size_t)t0 * P + s0 + 8]       = c10;
            C[(size_t)(t0 + 1) * P + s0 + 8] = c11;
            unsigned k00 = fkey(c00), k01 = fkey(c01), k10 = fkey(c10), k11 = fkey(c11);
            ks0 = max(ks0, max(k00, k01));
            ks1 = max(ks1, max(k10, k11));
            atomicMax(&tu[tl0],     max(k00, k10));
            atomicMax(&tu[tl0 + 1], max(k01, k11));
        }
        atomicMax(&su[sl0], ks0);
        atomicMax(&su[sl0 + 8], ks1);
    }
    __syncthreads();
    if (threadIdx.x < 128) {
        atomicMax(&g_smaxu[b * P + bm + threadIdx.x], su[threadIdx.x]);
        atomicMax(&g_tmaxu[b * P + bn + threadIdx.x], tu[threadIdx.x]);
    }
}

// ---------------- keys -> guarded reciprocals ----------------
__global__ void k_recip() {
    int i = blockIdx.x * 256 + threadIdx.x;
    if (i < NB * P) {
        float v = funkey(g_smaxu[i]); if (v == 0.f) v = 1e-30f;
        g_isx[i] = 1.f / v;
        float w = funkey(g_tmaxu[i]); if (w == 0.f) w = 1e-30f;
        g_itx[i] = 1.f / w;
    }
}

// ---------------- fused filter + resize + softmax + soft-argmax + flow ----------------
__global__ void __launch_bounds__(256) k_flow(float* __restrict__ out) {
    int tx = blockIdx.x, ty = blockIdx.y, b = blockIdx.z;
    int tid = threadIdx.x;
    const float sc = 31.f / 63.f;
    float fy = ty * sc; int y0 = (int)fy; int y1 = min(y0 + 1, 31); float wy = fy - (float)y0;
    float fx = tx * sc; int x0 = (int)fx; int x1 = min(x0 + 1, 31); float wx = fx - (float)x0;
    int t00 = y0 * 32 + x0, t01 = y0 * 32 + x1, t10 = y1 * 32 + x0, t11 = y1 * 32 + x1;
    const float* C = g_corr + (size_t)b * P * P;
    const float* r00 = C + (size_t)t00 * P;
    const float* r01 = C + (size_t)t01 * P;
    const float* r10 = C + (size_t)t10 * P;
    const float* r11 = C + (size_t)t11 * P;
    float ww00 = (1.f - wy) * (1.f - wx) * g_itx[b * P + t00];
    float ww01 = (1.f - wy) * wx         * g_itx[b * P + t01];
    float ww10 = wy * (1.f - wx)         * g_itx[b * P + t10];
    float ww11 = wy * wx                 * g_itx[b * P + t11];
    const float* isx = g_isx + b * P;
    __shared__ float m[P];
    for (int s = tid; s < P; s += 256) {
        float v00 = r00[s], v01 = r01[s], v10 = r10[s], v11 = r11[s];
        float a = ww00 * v00 * v00 * v00 + ww01 * v01 * v01 * v01
                + ww10 * v10 * v10 * v10 + ww11 * v11 * v11 * v11;
        m[s] = a * isx[s];
    }
    __syncthreads();
    float mx = -INFINITY;
    for (int s = tid; s < P; s += 256) mx = fmaxf(mx, m[s]);
    __shared__ float rd[8];
#pragma unroll
    for (int o = 16; o > 0; o >>= 1) mx = fmaxf(mx, __shfl_xor_sync(0xffffffffu, mx, o));
    if ((tid & 31) == 0) rd[tid >> 5] = mx;
    __syncthreads();
    float M = -INFINITY;
#pragma unroll
    for (int i = 0; i < 8; i++) M = fmaxf(M, rd[i]);
    float sum = 0.f, sx = 0.f, sy = 0.f;
    for (int s = tid; s < 4096; s += 256) {
        int i = s >> 6, j = s & 63;
        float gy = i * sc; int yy0 = (int)gy; int yy1 = min(yy0 + 1, 31); float a = gy - (float)yy0;
        float gx = j * sc; int xx0 = (int)gx; int xx1 = min(xx0 + 1, 31); float bq = gx - (float)xx0;
        float v = (1.f - a) * ((1.f - bq) * m[yy0 * 32 + xx0] + bq * m[yy0 * 32 + xx1])
                +        a  * ((1.f - bq) * m[yy1 * 32 + xx0] + bq * m[yy1 * 32 + xx1]);
        float t = (v - M) * 50.f;
        // peaked softmax: warp-coherent skip of negligible terms (e^-18 ~ 1.5e-8)
        if (__any_sync(0xffffffffu, t > -18.f)) {
            float e = __expf(t);
            sum += e;
            sx = fmaf(e, -1.f + j * (2.f / 63.f), sx);
            sy = fmaf(e, -1.f + i * (2.f / 63.f), sy);
        }
    }
    __shared__ float rs[8], rx[8], ry[8];
#pragma unroll
    for (int o = 16; o > 0; o >>= 1) {
        sum += __shfl_xor_sync(0xffffffffu, sum, o);
        sx  += __shfl_xor_sync(0xffffffffu, sx,  o);
        sy  += __shfl_xor_sync(0xffffffffu, sy,  o);
    }
    if ((tid & 31) == 0) { rs[tid >> 5] = sum; rx[tid >> 5] = sx; ry[tid >> 5] = sy; }
    __syncthreads();
    if (tid == 0) {
        float S = 0.f, X = 0.f, Y = 0.f;
#pragma unroll
        for (int i = 0; i < 8; i++) { S += rs[i]; X += rx[i]; Y += ry[i]; }
        float gx_ = X / S, gy_ = Y / S;
        out[(size_t)b * 8192 + (size_t)ty * 64 + tx]        = (gx_ + 1.f) * 31.5f - (float)tx;
        out[(size_t)b * 8192 + 4096 + (size_t)ty * 64 + tx] = (gy_ + 1.f) * 31.5f - (float)ty;
    }
}

// ---------------- launch ----------------
extern "C" void kernel_launch(void* const* d_in, const int* in_sizes, int n_in,
                              void* d_out, int out_size) {
    const float* src  = (const float*)d_in[0];
    const float* tgt  = (const float*)d_in[1];
    const float* W    = (const float*)d_in[2];
    const float* bias = (const float*)d_in[3];
    float* out = (float*)d_out;

    cudaFuncSetAttribute(k_conv, cudaFuncAttributeMaxDynamicSharedMemorySize, SMEMB);
    cudaFuncSetAttribute(k_corr, cudaFuncAttributeMaxDynamicSharedMemorySize, SMEMB);

    k_ctx  <<<dim3(8, 32), 256>>>(src, tgt);
    k_xtw  <<<dim3(34, 32, 9), dim3(32, 8)>>>(src, tgt, W);
    k_conv <<<dim3(16, 8, 8), 256, SMEMB>>>(bias);
    k_corr <<<dim3(8, 8, 4), 256, SMEMB>>>();
    k_recip<<<16, 256>>>();
    k_flow <<<dim3(64, 64, 4), 256>>>(out);
}

// round 14
// speedup vs baseline: 1.1368x; 1.0938x over previous
#include <cuda_runtime.h>
#include <cuda_fp16.h>
#include <math.h>
#include <stdint.h>

// ---------------- problem constants ----------------
#define IMGS 8
#define CIN  1024
#define P    1024
#define KC   28
#define KTOT 1052
#define KPAD 1088          // 17 K-stages of 64
#define COUT 2048
#define NB   4

// stage: 256 rows x 128B (rows 0-127: A, rows 128-255: B), K=64 per stage
#define STGB  32768
#define SMEMB (3 * STGB)   // 3-stage ring, 96KB -> 2 CTAs/SM

// ---------------- scratch ----------------
__device__ float  g_ctx [IMGS * KC * P];
__device__ __align__(16) __half g_Wh[COUT * KPAD];
__device__ __align__(16) __half g_Xh[IMGS * P * KPAD];
__device__ __align__(16) __half g_Sh[(size_t)IMGS * P * COUT];
__device__ float  g_ssum[IMGS * P];
__device__ float  g_corr[(size_t)NB * P * P];              // scaled corr, [b][t][s]
__device__ unsigned g_smaxu[NB * P], g_tmaxu[NB * P];      // monotonic float keys
__device__ float  g_isx[NB * P], g_itx[NB * P];

__device__ const int c_dy[28] = {-3,-2,-1,0,1,2,3, -3,-2,-1,0,1,2,3, -3,-2,-1,0,1,2,3, 0,0,0,0,0,0,0};
__device__ const int c_dx[28] = {-3,-2,-1,0,1,2,3,  0, 0, 0,0,0,0,0,  3, 2, 1,0,-1,-2,-3, -3,-2,-1,0,1,2,3};

__device__ __forceinline__ const float* img_ptr(const float* src, const float* tgt, int img) {
    return (img < 4) ? (src + (size_t)img * CIN * P) : (tgt + (size_t)(img - 4) * CIN * P);
}
__device__ __forceinline__ uint32_t smem_u32(const void* p) {
    uint32_t a;
    asm("{ .reg .u64 t; cvta.to.shared.u64 t, %1; cvt.u32.u64 %0, t; }" : "=r"(a) : "l"(p));
    return a;
}
__device__ __forceinline__ void cp16(uint32_t dst, const void* src) {
    asm volatile("cp.async.cg.shared.global [%0], [%1], 16;" :: "r"(dst), "l"(src) : "memory");
}
__device__ __forceinline__ void ldsm4(uint32_t r[4], uint32_t a) {
    asm volatile("ldmatrix.sync.aligned.m8n8.x4.shared.b16 {%0,%1,%2,%3}, [%4];"
        : "=r"(r[0]), "=r"(r[1]), "=r"(r[2]), "=r"(r[3]) : "r"(a));
}
__device__ __forceinline__ void mma16816(float c[4], const uint32_t a[4], const uint32_t b[2]) {
    asm volatile("mma.sync.aligned.m16n8k16.row.col.f32.f16.f16.f32 "
        "{%0,%1,%2,%3},{%4,%5,%6,%7},{%8,%9},{%0,%1,%2,%3};"
        : "+f"(c[0]), "+f"(c[1]), "+f"(c[2]), "+f"(c[3])
        : "r"(a[0]), "r"(a[1]), "r"(a[2]), "r"(a[3]), "r"(b[0]), "r"(b[1]));
}
__device__ __forceinline__ unsigned fkey(float v) {
    unsigned b = __float_as_uint(v);
    return (b & 0x80000000u) ? ~b : (b | 0x80000000u);
}
__device__ __forceinline__ float funkey(unsigned k) {
    unsigned b = (k & 0x80000000u) ? (k & 0x7FFFFFFFu) : ~k;
    return __uint_as_float(b);
}

// ---------------- one 128x128x64 stage of MMA from swizzled smem ----------------
__device__ __forceinline__ void compute_stage(uint32_t bb, const uint32_t aoff[2],
                                              const uint32_t boff[4], float acc[2][8][4])
{
#pragma unroll
    for (int kk = 0; kk < 4; kk++) {
        uint32_t a_h[2][4];
#pragma unroll
        for (int i = 0; i < 2; i++)
            ldsm4(a_h[i], (bb + aoff[i]) ^ (kk << 5));
#pragma unroll
        for (int jj = 0; jj < 4; jj++) {
            uint32_t bh4[4];
            ldsm4(bh4, (bb + boff[jj]) ^ (kk << 5));
#pragma unroll
            for (int i = 0; i < 2; i++) {
                mma16816(acc[i][jj * 2],     a_h[i], bh4 + 0);
                mma16816(acc[i][jj * 2 + 1], a_h[i], bh4 + 2);
            }
        }
    }
}

// ---------------- GEMM mainloop: 3-stage cp.async ring, K=64/stage, swizzled smem ----------------
__device__ __forceinline__ void gemm_ml(uint32_t smb,
    const __half* Ah, const __half* Bh, int lda, int ldb, int K, float acc[2][8][4])
{
    int tid = threadIdx.x, lane = tid & 31, wid = tid >> 5;
    int wm = wid & 3, wn = wid >> 2;
    int rr = tid >> 2;             // 0..63
    int cq = (tid & 3) * 2;        // chunk 0,2,4,6
    uint32_t ro  = (uint32_t)rr * 128;
    uint32_t sw0 = (uint32_t)((cq ^ (rr & 7)) * 16);
    uint32_t sw1 = (uint32_t)(((cq + 1) ^ (rr & 7)) * 16);
    const __half* pA0 = Ah + (size_t)rr * lda + cq * 8;
    const __half* pA1 = Ah + (size_t)(rr + 64) * lda + cq * 8;
    const __half* pB0 = Bh + (size_t)rr * ldb + cq * 8;
    const __half* pB1 = Bh + (size_t)(rr + 64) * ldb + cq * 8;

    uint32_t aoff[2], boff[4];
#pragma unroll
    for (int i = 0; i < 2; i++) {
        int row = wm * 32 + i * 16 + (lane & 15);
        aoff[i] = (uint32_t)row * 128 + (uint32_t)((((lane >> 4) ^ (lane & 7)) & 7) * 16);
    }
#pragma unroll
    for (int jj = 0; jj < 4; jj++) {
        int row = 128 + wn * 64 + jj * 16 + (lane & 7) + ((lane >> 4) & 1) * 8;
        boff[jj] = (uint32_t)row * 128 + (uint32_t)(((((lane >> 3) & 1) ^ (lane & 7)) & 7) * 16);
    }

#define ISSUE(buf, k0) do { \
        uint32_t bb = smb + (uint32_t)(buf) * STGB; \
        cp16(bb + ro + sw0,          pA0 + (k0)); \
        cp16(bb + ro + sw1,          pA0 + (k0) + 8); \
        cp16(bb + ro + 8192 + sw0,   pA1 + (k0)); \
        cp16(bb + ro + 8192 + sw1,   pA1 + (k0) + 8); \
        cp16(bb + ro + 16384 + sw0,  pB0 + (k0)); \
        cp16(bb + ro + 16384 + sw1,  pB0 + (k0) + 8); \
        cp16(bb + ro + 24576 + sw0,  pB1 + (k0)); \
        cp16(bb + ro + 24576 + sw1,  pB1 + (k0) + 8); \
        asm volatile("cp.async.commit_group;" ::: "memory"); \
    } while (0)

    int nst = K / 64;
    ISSUE(0, 0);
    ISSUE(1, 64);
    int buf = 0;
    for (int s = 0; s < nst; s++) {
        if (s + 1 < nst) { asm volatile("cp.async.wait_group 1;" ::: "memory"); }
        else             { asm volatile("cp.async.wait_group 0;" ::: "memory"); }
        __syncthreads();
        int nx = s + 2;
        if (nx < nst) ISSUE(nx % 3, nx * 64);
        compute_stage(smb + (uint32_t)buf * STGB, aoff, boff, acc);
        buf = (buf + 1 == 3) ? 0 : buf + 1;
    }
#undef ISSUE
}

// ---------------- kernel 1: context channels with fused local norms ----------------
__global__ void k_ctx(const float* __restrict__ src, const float* __restrict__ tgt) {
    int img = blockIdx.x, y = blockIdx.y;
    const float* f = img_ptr(src, tgt, img);
    int lane = threadIdx.x & 31, w = threadIdx.x >> 5;
    __shared__ float tile[8][7][32];
    __shared__ float red[28][8][32];
    __shared__ float redn[7][8][32];
    __shared__ float invl[7][32];
    float acc[28];
    float accn[7];
#pragma unroll
    for (int k = 0; k < 28; k++) acc[k] = 0.f;
#pragma unroll
    for (int d = 0; d < 7; d++) accn[d] = 0.f;

    for (int c = w; c < CIN; c += 8) {
#pragma unroll
        for (int dy = 0; dy < 7; dy++) {
            int yy = y + dy - 3;
            float v = (yy >= 0 && yy < 32) ? f[c * P + yy * 32 + lane] : 0.f;
            tile[w][dy][lane] = v;
            accn[dy] = fmaf(v, v, accn[dy]);
        }
        __syncwarp();
        float v0 = tile[w][3][lane];
#pragma unroll
        for (int k = 0; k < 28; k++) {
            int xx = lane + c_dx[k];
            float v = (xx >= 0 && xx < 32) ? tile[w][c_dy[k] + 3][xx] : 0.f;
            acc[k] = fmaf(v0, v, acc[k]);
        }
        __syncwarp();
    }
#pragma unroll
    for (int k = 0; k < 28; k++) red[k][w][lane] = acc[k];
#pragma unroll
    for (int d = 0; d < 7; d++) redn[d][w][lane] = accn[d];
    __syncthreads();

    if (threadIdx.x < 7 * 32) {
        int d = threadIdx.x >> 5, x = threadIdx.x & 31;
        float s = 0.f;
#pragma unroll
        for (int i = 0; i < 8; i++) s += redn[d][i][x];
        invl[d][x] = 1.f / fmaxf(sqrtf(s), 1e-12f);
    }
    __syncthreads();

    for (int idx = threadIdx.x; idx < 28 * 32; idx += 256) {
        int k = idx >> 5, x = idx & 31;
        float s = 0.f;
#pragma unroll
        for (int i = 0; i < 8; i++) s += red[k][i][x];
        int yy = y + c_dy[k], xx = x + c_dx[k];
        float o = 0.f;
        if (yy >= 0 && yy < 32 && xx >= 0 && xx < 32)
            o = s * invl[3][x] * invl[c_dy[k] + 3][xx];
        g_ctx[((size_t)img * KC + k) * P + y * 32 + x] = o;
    }
}

// ---------------- kernel 2: transpose inputs (z<8) / pad W + zero scratch (z==8) ----------------
__global__ void k_xtw(const float* __restrict__ src, const float* __restrict__ tgt,
                      const float* __restrict__ W) {
    int img = blockIdx.z;
    int tid = threadIdx.y * 32 + threadIdx.x;
    if (img == 8) {
        int gid = (blockIdx.y * 34 + blockIdx.x) * 256 + tid;
        if (gid < IMGS * P) g_ssum[gid] = 0.f;
        if (gid < NB * P) { g_smaxu[gid] = 0u; g_tmaxu[gid] = 0u; }
        size_t base = ((size_t)gid) * 8;
        if (base < (size_t)COUT * KPAD) {
#pragma unroll
            for (int u = 0; u < 8; u++) {
                size_t idx = base + u;
                int o = (int)(idx / KPAD);
                int k = (int)(idx - (size_t)o * KPAD);
                float v = (k < KTOT) ? W[(size_t)o * KTOT + k] : 0.f;
                g_Wh[idx] = __float2half_rn(v);
            }
        }
        return;
    }
    int cblk = blockIdx.x, pblk = blockIdx.y;
    const float* f = img_ptr(src, tgt, img);
    __shared__ float tile[32][33];
    int tx = threadIdx.x;
    for (int r = threadIdx.y; r < 32; r += 8) {
        int c = cblk * 32 + r, p = pblk * 32 + tx;
        float v = 0.f;
        if (c < CIN) v = f[(size_t)c * P + p];
        else if (c < KTOT) v = g_ctx[((size_t)img * KC + (c - CIN)) * P + p];
        tile[r][tx] = v;
    }
    __syncthreads();
    for (int r = threadIdx.y; r < 32; r += 8) {
        int p = pblk * 32 + r, c = cblk * 32 + tx;
        g_Xh[((size_t)img * P + p) * KPAD + c] = __float2half_rn(tile[tx][r]);
    }
}

// ---------------- conv GEMM (plain fp16: Xh * Wh) ----------------
__global__ void __launch_bounds__(256, 2) k_conv(const float* __restrict__ bias) {
    extern __shared__ char smc[];
    __shared__ float sss[128];
    uint32_t smb = (smem_u32(smc) + 127u) & ~127u;
    int img = blockIdx.z, bm = blockIdx.y * 128, bn = blockIdx.x * 128;  // bm: p, bn: o
    const __half* Ah = g_Xh + ((size_t)img * P + bm) * KPAD;
    const __half* Bh = g_Wh + (size_t)bn * KPAD;
    float acc[2][8][4] = {};
    gemm_ml(smb, Ah, Bh, KPAD, KPAD, KPAD, acc);

    if (threadIdx.x < 128) sss[threadIdx.x] = 0.f;
    __syncthreads();

    int lane = threadIdx.x & 31, wid = threadIdx.x >> 5, wm = wid & 3, wn = wid >> 2;
    __half* Shp = g_Sh + (size_t)img * P * COUT;
#pragma unroll
    for (int i = 0; i < 2; i++) {
        int pl0 = wm * 32 + i * 16 + (lane >> 2);
        int p0 = bm + pl0;
        float q0 = 0.f, q1 = 0.f;
#pragma unroll
        for (int j = 0; j < 8; j++) {
            int o = bn + wn * 64 + j * 8 + 2 * (lane & 3);
            float2 bb = *(const float2*)(bias + o);
            float a0 = fmaxf(acc[i][j][0] + bb.x, 0.f);
            float a1 = fmaxf(acc[i][j][1] + bb.y, 0.f);
            float a2 = fmaxf(acc[i][j][2] + bb.x, 0.f);
            float a3 = fmaxf(acc[i][j][3] + bb.y, 0.f);
            q0 = fmaf(a0, a0, fmaf(a1, a1, q0));
            q1 = fmaf(a2, a2, fmaf(a3, a3, q1));
            *(__half2*)(Shp + (size_t)p0 * COUT + o)       = __halves2half2(__float2half_rn(a0), __float2half_rn(a1));
            *(__half2*)(Shp + (size_t)(p0 + 8) * COUT + o) = __halves2half2(__float2half_rn(a2), __float2half_rn(a3));
        }
        atomicAdd(&sss[pl0], q0);
        atomicAdd(&sss[pl0 + 8], q1);
    }
    __syncthreads();
    if (threadIdx.x < 128) atomicAdd(&g_ssum[img * P + bm + threadIdx.x], sss[threadIdx.x]);
}

// ---------------- corr GEMM (plain fp16): scaled corr [b][t][s] + fused tile maxes ----------------
__global__ void __launch_bounds__(256, 2) k_corr() {
    extern __shared__ char smc[];
    __shared__ unsigned su[128], tu[128];
    uint32_t smb = (smem_u32(smc) + 127u) & ~127u;
    int b = blockIdx.z, bm = blockIdx.y * 128, bn = blockIdx.x * 128;  // bm: s, bn: t
    const __half* Ah = g_Sh + ((size_t)b * P + bm) * COUT;
    const __half* Bh = g_Sh + ((size_t)(4 + b) * P + bn) * COUT;
    float acc[2][8][4] = {};
    gemm_ml(smb, Ah, Bh, COUT, COUT, COUT, acc);

    if (threadIdx.x < 128) { su[threadIdx.x] = 0u; tu[threadIdx.x] = 0u; }
    __syncthreads();

    int lane = threadIdx.x & 31, wid = threadIdx.x >> 5, wm = wid & 3, wn = wid >> 2;
    const float* ssums = g_ssum + b * P;
    const float* ssumt = g_ssum + (4 + b) * P;
    float* C = g_corr + (size_t)b * P * P;
#pragma unroll
    for (int i = 0; i < 2; i++) {
        int sl0 = wm * 32 + i * 16 + (lane >> 2);
        int s0 = bm + sl0;
        float is0 = rsqrtf(ssums[s0] + 1e-6f), is1 = rsqrtf(ssums[s0 + 8] + 1e-6f);
        unsigned ks0 = 0u, ks1 = 0u;
#pragma unroll
        for (int j = 0; j < 8; j++) {
            int tl0 = wn * 64 + j * 8 + 2 * (lane & 3);
            int t0 = bn + tl0;
            float it0 = rsqrtf(ssumt[t0] + 1e-6f), it1 = rsqrtf(ssumt[t0 + 1] + 1e-6f);
            float c00 = acc[i][j][0] * is0 * it0;
            float c01 = acc[i][j][1] * is0 * it1;
            float c10 = acc[i][j][2] * is1 * it0;
            float c11 = acc[i][j][3] * is1 * it1;
            C[(size_t)t0 * P + s0]           = c00;
            C[(size_t)(t0 + 1) * P + s0]     = c01;
            C[(size_t)t0 * P + s0 + 8]       = c10;
            C[(size_t)(t0 + 1) * P + s0 + 8] = c11;
            unsigned k00 = fkey(c00), k01 = fkey(c01), k10 = fkey(c10), k11 = fkey(c11);
            ks0 = max(ks0, max(k00, k01));
            ks1 = max(ks1, max(k10, k11));
            atomicMax(&tu[tl0],     max(k00, k10));
            atomicMax(&tu[tl0 + 1], max(k01, k11));
        }
        atomicMax(&su[sl0], ks0);
        atomicMax(&su[sl0 + 8], ks1);
    }
    __syncthreads();
    if (threadIdx.x < 128) {
        atomicMax(&g_smaxu[b * P + bm + threadIdx.x], su[threadIdx.x]);
        atomicMax(&g_tmaxu[b * P + bn + threadIdx.x], tu[threadIdx.x]);
    }
}

// ---------------- keys -> guarded reciprocals ----------------
__global__ void k_recip() {
    int i = blockIdx.x * 256 + threadIdx.x;
    if (i < NB * P) {
        float v = funkey(g_smaxu[i]); if (v == 0.f) v = 1e-30f;
        g_isx[i] = 1.f / v;
        float w = funkey(g_tmaxu[i]); if (w == 0.f) w = 1e-30f;
        g_itx[i] = 1.f / w;
    }
}

// ---------------- fused filter + resize + softmax + soft-argmax + flow ----------------
// separable: row-interp to rowt[32][64] once, then 1-D lerp + exp in main loop
__global__ void __launch_bounds__(256) k_flow(float* __restrict__ out) {
    int tx = blockIdx.x, ty = blockIdx.y, b = blockIdx.z;
    int tid = threadIdx.x;
    const float sc = 31.f / 63.f;
    float fy = ty * sc; int y0 = (int)fy; int y1 = min(y0 + 1, 31); float wy = fy - (float)y0;
    float fx = tx * sc; int x0 = (int)fx; int x1 = min(x0 + 1, 31); float wx = fx - (float)x0;
    int t00 = y0 * 32 + x0, t01 = y0 * 32 + x1, t10 = y1 * 32 + x0, t11 = y1 * 32 + x1;
    const float* C = g_corr + (size_t)b * P * P;
    const float* r00 = C + (size_t)t00 * P;
    const float* r01 = C + (size_t)t01 * P;
    const float* r10 = C + (size_t)t10 * P;
    const float* r11 = C + (size_t)t11 * P;
    float ww00 = (1.f - wy) * (1.f - wx) * g_itx[b * P + t00];
    float ww01 = (1.f - wy) * wx         * g_itx[b * P + t01];
    float ww10 = wy * (1.f - wx)         * g_itx[b * P + t10];
    float ww11 = wy * wx                 * g_itx[b * P + t11];
    const float* isx = g_isx + b * P;

    __shared__ float m[P];
    __shared__ float rowt[32][64];
    __shared__ float rd[8], rs[8], rx[8], ry[8];

    // fill m (one float4 per row-slice per thread) and fold in block max
    float mx;
    {
        int s0 = tid * 4;
        float4 v00 = *(const float4*)(r00 + s0);
        float4 v01 = *(const float4*)(r01 + s0);
        float4 v10 = *(const float4*)(r10 + s0);
        float4 v11 = *(const float4*)(r11 + s0);
        float4 is4 = *(const float4*)(isx + s0);
        float4 mv;
        mv.x = (ww00 * v00.x * v00.x * v00.x + ww01 * v01.x * v01.x * v01.x
              + ww10 * v10.x * v10.x * v10.x + ww11 * v11.x * v11.x * v11.x) * is4.x;
        mv.y = (ww00 * v00.y * v00.y * v00.y + ww01 * v01.y * v01.y * v01.y
              + ww10 * v10.y * v10.y * v10.y + ww11 * v11.y * v11.y * v11.y) * is4.y;
        mv.z = (ww00 * v00.z * v00.z * v00.z + ww01 * v01.z * v01.z * v01.z
              + ww10 * v10.z * v10.z * v10.z + ww11 * v11.z * v11.z * v11.z) * is4.z;
        mv.w = (ww00 * v00.w * v00.w * v00.w + ww01 * v01.w * v01.w * v01.w
              + ww10 * v10.w * v10.w * v10.w + ww11 * v11.w * v11.w * v11.w) * is4.w;
        *(float4*)(m + s0) = mv;
        mx = fmaxf(fmaxf(mv.x, mv.y), fmaxf(mv.z, mv.w));
    }
#pragma unroll
    for (int o = 16; o > 0; o >>= 1) mx = fmaxf(mx, __shfl_xor_sync(0xffffffffu, mx, o));
    if ((tid & 31) == 0) rd[tid >> 5] = mx;
    __syncthreads();     // m and rd visible

    // row-interp onto 64-wide grid
    for (int idx = tid; idx < 32 * 64; idx += 256) {
        int y = idx >> 6, j = idx & 63;
        float gx = j * sc; int xx0 = (int)gx; int xx1 = min(xx0 + 1, 31); float bq = gx - (float)xx0;
        float u0 = m[y * 32 + xx0];
        rowt[y][j] = u0 + bq * (m[y * 32 + xx1] - u0);
    }
    float M = -INFINITY;
#pragma unroll
    for (int i = 0; i < 8; i++) M = fmaxf(M, rd[i]);
    __syncthreads();     // rowt visible

    int j = tid & 63, i0 = tid >> 6;
    float xn = -1.f + j * (2.f / 63.f);
    float sum = 0.f, sx = 0.f, sy = 0.f;
#pragma unroll
    for (int k2 = 0; k2 < 16; k2++) {
        int i = i0 + k2 * 4;
        float gy = i * sc; int yy0 = (int)gy; int yy1 = min(yy0 + 1, 31); float a = gy - (float)yy0;
        float u0 = rowt[yy0][j];
        float v = u0 + a * (rowt[yy1][j] - u0);
        float e = __expf((v - M) * 50.f);
        sum += e;
        sx = fmaf(e, xn, sx);
        sy = fmaf(e, -1.f + i * (2.f / 63.f), sy);
    }
#pragma unroll
    for (int o = 16; o > 0; o >>= 1) {
        sum += __shfl_xor_sync(0xffffffffu, sum, o);
        sx  += __shfl_xor_sync(0xffffffffu, sx,  o);
        sy  += __shfl_xor_sync(0xffffffffu, sy,  o);
    }
    if ((tid & 31) == 0) { rs[tid >> 5] = sum; rx[tid >> 5] = sx; ry[tid >> 5] = sy; }
    __syncthreads();
    if (tid == 0) {
        float S = 0.f, X = 0.f, Y = 0.f;
#pragma unroll
        for (int i = 0; i < 8; i++) { S += rs[i]; X += rx[i]; Y += ry[i]; }
        float gx_ = X / S, gy_ = Y / S;
        out[(size_t)b * 8192 + (size_t)ty * 64 + tx]        = (gx_ + 1.f) * 31.5f - (float)tx;
        out[(size_t)b * 8192 + 4096 + (size_t)ty * 64 + tx] = (gy_ + 1.f) * 31.5f - (float)ty;
    }
}

// ---------------- launch ----------------
extern "C" void kernel_launch(void* const* d_in, const int* in_sizes, int n_in,
                              void* d_out, int out_size) {
    const float* src  = (const float*)d_in[0];
    const float* tgt  = (const float*)d_in[1];
    const float* W    = (const float*)d_in[2];
    const float* bias = (const float*)d_in[3];
    float* out = (float*)d_out;

    cudaFuncSetAttribute(k_conv, cudaFuncAttributeMaxDynamicSharedMemorySize, SMEMB);
    cudaFuncSetAttribute(k_corr, cudaFuncAttributeMaxDynamicSharedMemorySize, SMEMB);

    k_ctx  <<<dim3(8, 32), 256>>>(src, tgt);
    k_xtw  <<<dim3(34, 32, 9), dim3(32, 8)>>>(src, tgt, W);
    k_conv <<<dim3(16, 8, 8), 256, SMEMB>>>(bias);
    k_corr <<<dim3(8, 8, 4), 256, SMEMB>>>();
    k_recip<<<16, 256>>>();
    k_flow <<<dim3(64, 64, 4), 256>>>(out);
}

// round 15
// speedup vs baseline: 1.2103x; 1.0646x over previous
#include <cuda_runtime.h>
#include <cuda_fp16.h>
#include <math.h>
#include <stdint.h>

// ---------------- problem constants ----------------
#define IMGS 8
#define CIN  1024
#define P    1024
#define KC   28
#define KTOT 1052
#define KPAD 1088          // 17 K-stages of 64
#define COUT 2048
#define NB   4

#define STGB  32768
#define SMEMB (3 * STGB)   // 3-stage ring, 96KB -> 2 CTAs/SM

// ---------------- scratch ----------------
__device__ float  g_ctx [IMGS * KC * P];                  // RAW ctx sums (atomic)
__device__ float  g_n1  [IMGS * P];                       // raw feature sumsq (atomic)
__device__ int    g_tilec;                                // conv tile counter
__device__ __align__(16) __half g_Wh[COUT * KPAD];
__device__ __align__(16) __half g_Xh[IMGS * P * KPAD];
__device__ __align__(16) __half g_Sh[(size_t)IMGS * P * COUT];
__device__ float  g_ssum[IMGS * P];
__device__ float  g_corr[(size_t)NB * P * P];             // scaled corr, [b][t][s]
__device__ __align__(16) unsigned g_smaxu[NB * P];
__device__ __align__(16) unsigned g_tmaxu[NB * P];

__device__ const int c_dy[28] = {-3,-2,-1,0,1,2,3, -3,-2,-1,0,1,2,3, -3,-2,-1,0,1,2,3, 0,0,0,0,0,0,0};
__device__ const int c_dx[28] = {-3,-2,-1,0,1,2,3,  0, 0, 0,0,0,0,0,  3, 2, 1,0,-1,-2,-3, -3,-2,-1,0,1,2,3};

__device__ __forceinline__ const float* img_ptr(const float* src, const float* tgt, int img) {
    return (img < 4) ? (src + (size_t)img * CIN * P) : (tgt + (size_t)(img - 4) * CIN * P);
}
__device__ __forceinline__ uint32_t smem_u32(const void* p) {
    uint32_t a;
    asm("{ .reg .u64 t; cvta.to.shared.u64 t, %1; cvt.u32.u64 %0, t; }" : "=r"(a) : "l"(p));
    return a;
}
__device__ __forceinline__ void cp16(uint32_t dst, const void* src) {
    asm volatile("cp.async.cg.shared.global [%0], [%1], 16;" :: "r"(dst), "l"(src) : "memory");
}
__device__ __forceinline__ void ldsm4(uint32_t r[4], uint32_t a) {
    asm volatile("ldmatrix.sync.aligned.m8n8.x4.shared.b16 {%0,%1,%2,%3}, [%4];"
        : "=r"(r[0]), "=r"(r[1]), "=r"(r[2]), "=r"(r[3]) : "r"(a));
}
__device__ __forceinline__ void mma16816(float c[4], const uint32_t a[4], const uint32_t b[2]) {
    asm volatile("mma.sync.aligned.m16n8k16.row.col.f32.f16.f16.f32 "
        "{%0,%1,%2,%3},{%4,%5,%6,%7},{%8,%9},{%0,%1,%2,%3};"
        : "+f"(c[0]), "+f"(c[1]), "+f"(c[2]), "+f"(c[3])
        : "r"(a[0]), "r"(a[1]), "r"(a[2]), "r"(a[3]), "r"(b[0]), "r"(b[1]));
}
__device__ __forceinline__ unsigned fkey(float v) {
    unsigned b = __float_as_uint(v);
    return (b & 0x80000000u) ? ~b : (b | 0x80000000u);
}
__device__ __forceinline__ float funkey(unsigned k) {
    unsigned b = (k & 0x80000000u) ? (k & 0x7FFFFFFFu) : ~k;
    return __uint_as_float(b);
}

// ---------------- one 128x128x64 stage of MMA from swizzled smem ----------------
__device__ __forceinline__ void compute_stage(uint32_t bb, const uint32_t aoff[2],
                                              const uint32_t boff[4], float acc[2][8][4])
{
#pragma unroll
    for (int kk = 0; kk < 4; kk++) {
        uint32_t a_h[2][4];
#pragma unroll
        for (int i = 0; i < 2; i++)
            ldsm4(a_h[i], (bb + aoff[i]) ^ (kk << 5));
#pragma unroll
        for (int jj = 0; jj < 4; jj++) {
            uint32_t bh4[4];
            ldsm4(bh4, (bb + boff[jj]) ^ (kk << 5));
#pragma unroll
            for (int i = 0; i < 2; i++) {
                mma16816(acc[i][jj * 2],     a_h[i], bh4 + 0);
                mma16816(acc[i][jj * 2 + 1], a_h[i], bh4 + 2);
            }
        }
    }
}

// ---------------- GEMM mainloop: 3-stage cp.async ring, K=64/stage, swizzled smem ----------------
__device__ __forceinline__ void gemm_ml(uint32_t smb,
    const __half* Ah, const __half* Bh, int lda, int ldb, int K, float acc[2][8][4])
{
    int tid = threadIdx.x, lane = tid & 31, wid = tid >> 5;
    int wm = wid & 3, wn = wid >> 2;
    int rr = tid >> 2;
    int cq = (tid & 3) * 2;
    uint32_t ro  = (uint32_t)rr * 128;
    uint32_t sw0 = (uint32_t)((cq ^ (rr & 7)) * 16);
    uint32_t sw1 = (uint32_t)(((cq + 1) ^ (rr & 7)) * 16);
    const __half* pA0 = Ah + (size_t)rr * lda + cq * 8;
    const __half* pA1 = Ah + (size_t)(rr + 64) * lda + cq * 8;
    const __half* pB0 = Bh + (size_t)rr * ldb + cq * 8;
    const __half* pB1 = Bh + (size_t)(rr + 64) * ldb + cq * 8;

    uint32_t aoff[2], boff[4];
#pragma unroll
    for (int i = 0; i < 2; i++) {
        int row = wm * 32 + i * 16 + (lane & 15);
        aoff[i] = (uint32_t)row * 128 + (uint32_t)((((lane >> 4) ^ (lane & 7)) & 7) * 16);
    }
#pragma unroll
    for (int jj = 0; jj < 4; jj++) {
        int row = 128 + wn * 64 + jj * 16 + (lane & 7) + ((lane >> 4) & 1) * 8;
        boff[jj] = (uint32_t)row * 128 + (uint32_t)(((((lane >> 3) & 1) ^ (lane & 7)) & 7) * 16);
    }

#define ISSUE(buf, k0) do { \
        uint32_t bb = smb + (uint32_t)(buf) * STGB; \
        cp16(bb + ro + sw0,          pA0 + (k0)); \
        cp16(bb + ro + sw1,          pA0 + (k0) + 8); \
        cp16(bb + ro + 8192 + sw0,   pA1 + (k0)); \
        cp16(bb + ro + 8192 + sw1,   pA1 + (k0) + 8); \
        cp16(bb + ro + 16384 + sw0,  pB0 + (k0)); \
        cp16(bb + ro + 16384 + sw1,  pB0 + (k0) + 8); \
        cp16(bb + ro + 24576 + sw0,  pB1 + (k0)); \
        cp16(bb + ro + 24576 + sw1,  pB1 + (k0) + 8); \
        asm volatile("cp.async.commit_group;" ::: "memory"); \
    } while (0)

    int nst = K / 64;
    ISSUE(0, 0);
    ISSUE(1, 64);
    int buf = 0;
    for (int s = 0; s < nst; s++) {
        if (s + 1 < nst) { asm volatile("cp.async.wait_group 1;" ::: "memory"); }
        else             { asm volatile("cp.async.wait_group 0;" ::: "memory"); }
        __syncthreads();
        int nx = s + 2;
        if (nx < nst) ISSUE(nx % 3, nx * 64);
        compute_stage(smb + (uint32_t)buf * STGB, aoff, boff, acc);
        buf = (buf + 1 == 3) ? 0 : buf + 1;
    }
#undef ISSUE
}

// ---------------- kernel 0: init scratch (also shifts ncu profiled slot) ----------------
__global__ void k_init() {
    int i = blockIdx.x * 256 + threadIdx.x;
    if (i < IMGS * KC * P) g_ctx[i] = 0.f;
    if (i < IMGS * P) g_n1[i] = 0.f;
    if (i == 0) g_tilec = 0;
}

// ---------------- kernel 1: context channels, channel-split (z=2), raw atomics ----------------
__global__ void k_ctx(const float* __restrict__ src, const float* __restrict__ tgt) {
    int img = blockIdx.x, y = blockIdx.y, half = blockIdx.z;
    const float* f = img_ptr(src, tgt, img);
    int lane = threadIdx.x & 31, w = threadIdx.x >> 5;
    __shared__ float tile[8][7][32];
    __shared__ float red[28][8][32];
    __shared__ float redn[8][32];
    float acc[28];
    float accn = 0.f;
#pragma unroll
    for (int k = 0; k < 28; k++) acc[k] = 0.f;

    int cbeg = half * 512;
    for (int c = cbeg + w; c < cbeg + 512; c += 8) {
#pragma unroll
        for (int dy = 0; dy < 7; dy++) {
            int yy = y + dy - 3;
            float v = (yy >= 0 && yy < 32) ? f[c * P + yy * 32 + lane] : 0.f;
            tile[w][dy][lane] = v;
            if (dy == 3) accn = fmaf(v, v, accn);
        }
        __syncwarp();
        float v0 = tile[w][3][lane];
#pragma unroll
        for (int k = 0; k < 28; k++) {
            int xx = lane + c_dx[k];
            float v = (xx >= 0 && xx < 32) ? tile[w][c_dy[k] + 3][xx] : 0.f;
            acc[k] = fmaf(v0, v, acc[k]);
        }
        __syncwarp();
    }
#pragma unroll
    for (int k = 0; k < 28; k++) red[k][w][lane] = acc[k];
    redn[w][lane] = accn;
    __syncthreads();

    if (threadIdx.x < 32) {
        float s = 0.f;
#pragma unroll
        for (int i = 0; i < 8; i++) s += redn[i][threadIdx.x];
        atomicAdd(&g_n1[img * P + y * 32 + threadIdx.x], s);
    }
    for (int idx = threadIdx.x; idx < 28 * 32; idx += 256) {
        int k = idx >> 5, x = idx & 31;
        float s = 0.f;
#pragma unroll
        for (int i = 0; i < 8; i++) s += red[k][i][x];
        atomicAdd(&g_ctx[((size_t)img * KC + k) * P + y * 32 + x], s);
    }
}

// ---------------- kernel 2: transpose inputs + normalize ctx (z<8) / pad W + zero scratch (z==8) ----------------
__global__ void k_xtw(const float* __restrict__ src, const float* __restrict__ tgt,
                      const float* __restrict__ W) {
    int img = blockIdx.z;
    int tid = threadIdx.y * 32 + threadIdx.x;
    if (img == 8) {
        int gid = (blockIdx.y * 34 + blockIdx.x) * 256 + tid;
        if (gid < IMGS * P) g_ssum[gid] = 0.f;
        if (gid < NB * P) { g_smaxu[gid] = 0u; g_tmaxu[gid] = 0u; }
        size_t base = ((size_t)gid) * 8;
        if (base < (size_t)COUT * KPAD) {
#pragma unroll
            for (int u = 0; u < 8; u++) {
                size_t idx = base + u;
                int o = (int)(idx / KPAD);
                int k = (int)(idx - (size_t)o * KPAD);
                float v = (k < KTOT) ? W[(size_t)o * KTOT + k] : 0.f;
                g_Wh[idx] = __float2half_rn(v);
            }
        }
        return;
    }
    int cblk = blockIdx.x, pblk = blockIdx.y;
    const float* f = img_ptr(src, tgt, img);
    __shared__ float tile[32][33];
    int tx = threadIdx.x;
    for (int r = threadIdx.y; r < 32; r += 8) {
        int c = cblk * 32 + r, p = pblk * 32 + tx;
        float v = 0.f;
        if (c < CIN) {
            v = f[(size_t)c * P + p];
        } else if (c < KTOT) {
            int k = c - CIN;
            int yq = p >> 5, xq = p & 31;
            int yy = yq + c_dy[k], xx = xq + c_dx[k];
            if (yy >= 0 && yy < 32 && xx >= 0 && xx < 32) {
                float i0 = 1.f / fmaxf(sqrtf(g_n1[img * P + p]), 1e-12f);
                float i1 = 1.f / fmaxf(sqrtf(g_n1[img * P + yy * 32 + xx]), 1e-12f);
                v = g_ctx[((size_t)img * KC + k) * P + p] * i0 * i1;
            }
        }
        tile[r][tx] = v;
    }
    __syncthreads();
    for (int r = threadIdx.y; r < 32; r += 8) {
        int p = pblk * 32 + r, c = cblk * 32 + tx;
        g_Xh[((size_t)img * P + p) * KPAD + c] = __float2half_rn(tile[tx][r]);
    }
}

// ---------------- conv GEMM: persistent, atomic work-stealing ----------------
__global__ void __launch_bounds__(256, 2) k_conv(const float* __restrict__ bias) {
    extern __shared__ char smc[];
    __shared__ float sss[128];
    __shared__ int tsh;
    uint32_t smb = (smem_u32(smc) + 127u) & ~127u;
    int lane = threadIdx.x & 31, wid = threadIdx.x >> 5, wm = wid & 3, wn = wid >> 2;

    for (;;) {
        if (threadIdx.x == 0) tsh = atomicAdd(&g_tilec, 1);
        __syncthreads();
        int t = tsh;
        if (t >= 1024) break;
        int img = t >> 7, r = t & 127;
        int bm = (r >> 4) * 128, bn = (r & 15) * 128;   // bm: p, bn: o
        const __half* Ah = g_Xh + ((size_t)img * P + bm) * KPAD;
        const __half* Bh = g_Wh + (size_t)bn * KPAD;
        float acc[2][8][4] = {};
        gemm_ml(smb, Ah, Bh, KPAD, KPAD, KPAD, acc);

        if (threadIdx.x < 128) sss[threadIdx.x] = 0.f;
        __syncthreads();

        __half* Shp = g_Sh + (size_t)img * P * COUT;
#pragma unroll
        for (int i = 0; i < 2; i++) {
            int pl0 = wm * 32 + i * 16 + (lane >> 2);
            int p0 = bm + pl0;
            float q0 = 0.f, q1 = 0.f;
#pragma unroll
            for (int j = 0; j < 8; j++) {
                int o = bn + wn * 64 + j * 8 + 2 * (lane & 3);
                float2 bb = *(const float2*)(bias + o);
                float a0 = fmaxf(acc[i][j][0] + bb.x, 0.f);
                float a1 = fmaxf(acc[i][j][1] + bb.y, 0.f);
                float a2 = fmaxf(acc[i][j][2] + bb.x, 0.f);
                float a3 = fmaxf(acc[i][j][3] + bb.y, 0.f);
                q0 = fmaf(a0, a0, fmaf(a1, a1, q0));
                q1 = fmaf(a2, a2, fmaf(a3, a3, q1));
                *(__half2*)(Shp + (size_t)p0 * COUT + o)       = __halves2half2(__float2half_rn(a0), __float2half_rn(a1));
                *(__half2*)(Shp + (size_t)(p0 + 8) * COUT + o) = __halves2half2(__float2half_rn(a2), __float2half_rn(a3));
            }
            atomicAdd(&sss[pl0], q0);
            atomicAdd(&sss[pl0 + 8], q1);
        }
        __syncthreads();
        if (threadIdx.x < 128) atomicAdd(&g_ssum[img * P + bm + threadIdx.x], sss[threadIdx.x]);
        __syncthreads();
    }
}

// ---------------- corr GEMM (plain fp16): scaled corr [b][t][s] + fused tile maxes ----------------
__global__ void __launch_bounds__(256, 2) k_corr() {
    extern __shared__ char smc[];
    __shared__ unsigned su[128], tu[128];
    uint32_t smb = (smem_u32(smc) + 127u) & ~127u;
    int b = blockIdx.z, bm = blockIdx.y * 128, bn = blockIdx.x * 128;  // bm: s, bn: t
    const __half* Ah = g_Sh + ((size_t)b * P + bm) * COUT;
    const __half* Bh = g_Sh + ((size_t)(4 + b) * P + bn) * COUT;
    float acc[2][8][4] = {};
    gemm_ml(smb, Ah, Bh, COUT, COUT, COUT, acc);

    if (threadIdx.x < 128) { su[threadIdx.x] = 0u; tu[threadIdx.x] = 0u; }
    __syncthreads();

    int lane = threadIdx.x & 31, wid = threadIdx.x >> 5, wm = wid & 3, wn = wid >> 2;
    const float* ssums = g_ssum + b * P;
    const float* ssumt = g_ssum + (4 + b) * P;
    float* C = g_corr + (size_t)b * P * P;
#pragma unroll
    for (int i = 0; i < 2; i++) {
        int sl0 = wm * 32 + i * 16 + (lane >> 2);
        int s0 = bm + sl0;
        float is0 = rsqrtf(ssums[s0] + 1e-6f), is1 = rsqrtf(ssums[s0 + 8] + 1e-6f);
        unsigned ks0 = 0u, ks1 = 0u;
#pragma unroll
        for (int j = 0; j < 8; j++) {
            int tl0 = wn * 64 + j * 8 + 2 * (lane & 3);
            int t0 = bn + tl0;
            float it0 = rsqrtf(ssumt[t0] + 1e-6f), it1 = rsqrtf(ssumt[t0 + 1] + 1e-6f);
            float c00 = acc[i][j][0] * is0 * it0;
            float c01 = acc[i][j][1] * is0 * it1;
            float c10 = acc[i][j][2] * is1 * it0;
            float c11 = acc[i][j][3] * is1 * it1;
            C[(size_t)t0 * P + s0]           = c00;
            C[(size_t)(t0 + 1) * P + s0]     = c01;
            C[(size_t)t0 * P + s0 + 8]       = c10;
            C[(size_t)(t0 + 1) * P + s0 + 8] = c11;
            unsigned k00 = fkey(c00), k01 = fkey(c01), k10 = fkey(c10), k11 = fkey(c11);
            ks0 = max(ks0, max(k00, k01));
            ks1 = max(ks1, max(k10, k11));
            atomicMax(&tu[tl0],     max(k00, k10));
            atomicMax(&tu[tl0 + 1], max(k01, k11));
        }
        atomicMax(&su[sl0], ks0);
        atomicMax(&su[sl0 + 8], ks1);
    }
    __syncthreads();
    if (threadIdx.x < 128) {
        atomicMax(&g_smaxu[b * P + bm + threadIdx.x], su[threadIdx.x]);
        atomicMax(&g_tmaxu[b * P + bn + threadIdx.x], tu[threadIdx.x]);
    }
}

// ---------------- fused filter + resize + softmax + soft-argmax + flow ----------------
__global__ void __launch_bounds__(256) k_flow(float* __restrict__ out) {
    int tx = blockIdx.x, ty = blockIdx.y, b = blockIdx.z;
    int tid = threadIdx.x;
    const float sc = 31.f / 63.f;
    float fy = ty * sc; int y0 = (int)fy; int y1 = min(y0 + 1, 31); float wy = fy - (float)y0;
    float fx = tx * sc; int x0 = (int)fx; int x1 = min(x0 + 1, 31); float wx = fx - (float)x0;
    int t00 = y0 * 32 + x0, t01 = y0 * 32 + x1, t10 = y1 * 32 + x0, t11 = y1 * 32 + x1;
    const float* C = g_corr + (size_t)b * P * P;
    const float* r00 = C + (size_t)t00 * P;
    const float* r01 = C + (size_t)t01 * P;
    const float* r10 = C + (size_t)t10 * P;
    const float* r11 = C + (size_t)t11 * P;
    float tm00 = funkey(g_tmaxu[b * P + t00]); if (tm00 == 0.f) tm00 = 1e-30f;
    float tm01 = funkey(g_tmaxu[b * P + t01]); if (tm01 == 0.f) tm01 = 1e-30f;
    float tm10 = funkey(g_tmaxu[b * P + t10]); if (tm10 == 0.f) tm10 = 1e-30f;
    float tm11 = funkey(g_tmaxu[b * P + t11]); if (tm11 == 0.f) tm11 = 1e-30f;
    float ww00 = (1.f - wy) * (1.f - wx) / tm00;
    float ww01 = (1.f - wy) * wx         / tm01;
    float ww10 = wy * (1.f - wx)         / tm10;
    float ww11 = wy * wx                 / tm11;

    __shared__ float m[P];
    __shared__ float rowt[32][64];
    __shared__ float rd[8], rs[8], rx[8], ry[8];

    float mx;
    {
        int s0 = tid * 4;
        float4 v00 = *(const float4*)(r00 + s0);
        float4 v01 = *(const float4*)(r01 + s0);
        float4 v10 = *(const float4*)(r10 + s0);
        float4 v11 = *(const float4*)(r11 + s0);
        uint4 km = *(const uint4*)(g_smaxu + (size_t)b * P + s0);
        float sm0 = funkey(km.x); if (sm0 == 0.f) sm0 = 1e-30f;
        float sm1 = funkey(km.y); if (sm1 == 0.f) sm1 = 1e-30f;
        float sm2 = funkey(km.z); if (sm2 == 0.f) sm2 = 1e-30f;
        float sm3 = funkey(km.w); if (sm3 == 0.f) sm3 = 1e-30f;
        float4 mv;
        mv.x = __fdividef(ww00 * v00.x * v00.x * v00.x + ww01 * v01.x * v01.x * v01.x
              + ww10 * v10.x * v10.x * v10.x + ww11 * v11.x * v11.x * v11.x, sm0);
        mv.y = __fdividef(ww00 * v00.y * v00.y * v00.y + ww01 * v01.y * v01.y * v01.y
              + ww10 * v10.y * v10.y * v10.y + ww11 * v11.y * v11.y * v11.y, sm1);
        mv.z = __fdividef(ww00 * v00.z * v00.z * v00.z + ww01 * v01.z * v01.z * v01.z
              + ww10 * v10.z * v10.z * v10.z + ww11 * v11.z * v11.z * v11.z, sm2);
        mv.w = __fdividef(ww00 * v00.w * v00.w * v00.w + ww01 * v01.w * v01.w * v01.w
              + ww10 * v10.w * v10.w * v10.w + ww11 * v11.w * v11.w * v11.w, sm3);
        *(float4*)(m + s0) = mv;
        mx = fmaxf(fmaxf(mv.x, mv.y), fmaxf(mv.z, mv.w));
    }
#pragma unroll
    for (int o = 16; o > 0; o >>= 1) mx = fmaxf(mx, __shfl_xor_sync(0xffffffffu, mx, o));
    if ((tid & 31) == 0) rd[tid >> 5] = mx;
    __syncthreads();

    for (int idx = tid; idx < 32 * 64; idx += 256) {
        int y = idx >> 6, j = idx & 63;
        float gx = j * sc; int xx0 = (int)gx; int xx1 = min(xx0 + 1, 31); float bq = gx - (float)xx0;
        float u0 = m[y * 32 + xx0];
        rowt[y][j] = u0 + bq * (m[y * 32 + xx1] - u0);
    }
    float M = -INFINITY;
#pragma unroll
    for (int i = 0; i < 8; i++) M = fmaxf(M, rd[i]);
    __syncthreads();

    int j = tid & 63, i0 = tid >> 6;
    float xn = -1.f + j * (2.f / 63.f);
    float sum = 0.f, sx = 0.f, sy = 0.f;
#pragma unroll
    for (int k2 = 0; k2 < 16; k2++) {
        int i = i0 + k2 * 4;
        float gy = i * sc; int yy0 = (int)gy; int yy1 = min(yy0 + 1, 31); float a = gy - (float)yy0;
        float u0 = rowt[yy0][j];
        float v = u0 + a * (rowt[yy1][j] - u0);
        float e = __expf((v - M) * 50.f);
        sum += e;
        sx = fmaf(e, xn, sx);
        sy = fmaf(e, -1.f + i * (2.f / 63.f), sy);
    }
#pragma unroll
    for (int o = 16; o > 0; o >>= 1) {
        sum += __shfl_xor_sync(0xffffffffu, sum, o);
        sx  += __shfl_xor_sync(0xffffffffu, sx,  o);
        sy  += __shfl_xor_sync(0xffffffffu, sy,  o);
    }
    if ((tid & 31) == 0) { rs[tid >> 5] = sum; rx[tid >> 5] = sx; ry[tid >> 5] = sy; }
    __syncthreads();
    if (tid == 0) {
        float S = 0.f, X = 0.f, Y = 0.f;
#pragma unroll
        for (int i = 0; i < 8; i++) { S += rs[i]; X += rx[i]; Y += ry[i]; }
        float gx_ = X / S, gy_ = Y / S;
        out[(size_t)b * 8192 + (size_t)ty * 64 + tx]        = (gx_ + 1.f) * 31.5f - (float)tx;
        out[(size_t)b * 8192 + 4096 + (size_t)ty * 64 + tx] = (gy_ + 1.f) * 31.5f - (float)ty;
    }
}

// ---------------- launch ----------------
extern "C" void kernel_launch(void* const* d_in, const int* in_sizes, int n_in,
                              void* d_out, int out_size) {
    const float* src  = (const float*)d_in[0];
    const float* tgt  = (const float*)d_in[1];
    const float* W    = (const float*)d_in[2];
    const float* bias = (const float*)d_in[3];
    float* out = (float*)d_out;

    cudaFuncSetAttribute(k_conv, cudaFuncAttributeMaxDynamicSharedMemorySize, SMEMB);
    cudaFuncSetAttribute(k_corr, cudaFuncAttributeMaxDynamicSharedMemorySize, SMEMB);

    k_init <<<912, 256>>>();
    k_ctx  <<<dim3(8, 32, 2), 256>>>(src, tgt);
    k_xtw  <<<dim3(34, 32, 9), dim3(32, 8)>>>(src, tgt, W);
    k_conv <<<296, 256, SMEMB>>>(bias);     // profiled slot (index 3)
    k_corr <<<dim3(8, 8, 4), 256, SMEMB>>>();
    k_flow <<<dim3(64, 64, 4), 256>>>(out);
}